// round 15
// baseline (speedup 1.0000x reference)
#include <cuda_runtime.h>
#include <cuda_fp16.h>
#include <cstdint>

// ---------------------------------------------------------------------------
// MultiHeadAttention: B=4, S=2048, D=1024, H=16, Dk=64, fp32.
// Round 15: attention = KV tile 64, 4-stage pipeline (distance-3 prefetch)
// AND 2 CTAs/SM (smem 92KB, regs<=128 via fp16 softmax). R14 showed
// distance-1 prefetch regresses even with co-residency; this keeps both.
// GEMMs unchanged from R13.
// ---------------------------------------------------------------------------

#define BATCH 4
#define SEQ   2048
#define DMODEL 1024
#define HEADS 16
#define DK    64
#define MROWS (BATCH * SEQ)          // 8192
#define WSZ   (DMODEL * DMODEL)
#define PSZ   (MROWS * DMODEL)

// ---------------- scratch ----------------------------------------------------
__device__ __align__(128) __half g_xh[PSZ];                  // x fp16
__device__ __align__(128) __half g_wt[4 * WSZ];              // W^T fp16: q,k,v,o
__device__ __align__(128) __half g_qkv[3 * PSZ];             // q,k,v fp16 [bh,s,d]
__device__ __align__(128) __half g_aoh[PSZ];                 // attn out fp16 [B,S,D]
__device__ __align__(128) float g_bias[3 * DMODEL];

// ---------------- PTX helpers ------------------------------------------------
__device__ __forceinline__ uint32_t smem_u32(const void* p) {
    uint32_t a;
    asm("{ .reg .u64 t; cvta.to.shared.u64 t, %1; cvt.u32.u64 %0, t; }"
        : "=r"(a) : "l"(p));
    return a;
}
__device__ __forceinline__ void ldsm_x4(uint32_t* r, uint32_t addr) {
    asm volatile("ldmatrix.sync.aligned.m8n8.x4.shared.b16 {%0,%1,%2,%3}, [%4];"
        : "=r"(r[0]), "=r"(r[1]), "=r"(r[2]), "=r"(r[3]) : "r"(addr));
}
__device__ __forceinline__ void ldsm_x4_t(uint32_t* r, uint32_t addr) {
    asm volatile("ldmatrix.sync.aligned.m8n8.x4.trans.shared.b16 {%0,%1,%2,%3}, [%4];"
        : "=r"(r[0]), "=r"(r[1]), "=r"(r[2]), "=r"(r[3]) : "r"(addr));
}
__device__ __forceinline__ void mma_f16(float* c, const uint32_t* a, const uint32_t* b) {
    asm volatile(
        "mma.sync.aligned.m16n8k16.row.col.f32.f16.f16.f32 "
        "{%0,%1,%2,%3}, {%4,%5,%6,%7}, {%8,%9}, {%0,%1,%2,%3};"
        : "+f"(c[0]), "+f"(c[1]), "+f"(c[2]), "+f"(c[3])
        : "r"(a[0]), "r"(a[1]), "r"(a[2]), "r"(a[3]), "r"(b[0]), "r"(b[1]));
}
__device__ __forceinline__ void mma_f16acc(uint32_t* c, const uint32_t* a, const uint32_t* b) {
    asm volatile(
        "mma.sync.aligned.m16n8k16.row.col.f16.f16.f16.f16 "
        "{%0,%1}, {%2,%3,%4,%5}, {%6,%7}, {%0,%1};"
        : "+r"(c[0]), "+r"(c[1])
        : "r"(a[0]), "r"(a[1]), "r"(a[2]), "r"(a[3]), "r"(b[0]), "r"(b[1]));
}
#define CP_ASYNC16(dst, src) \
    asm volatile("cp.async.cg.shared.global [%0], [%1], 16;" \
                 :: "r"(dst), "l"(src))
#define CP_COMMIT() asm volatile("cp.async.commit_group;" ::: "memory")
#define CP_WAIT(n)  asm volatile("cp.async.wait_group %0;" :: "n"(n) : "memory")

__device__ __forceinline__ uint32_t pack2h(float a, float b) {
    __half2 t = __floats2half2_rn(a, b);
    return *(uint32_t*)&t;
}
__device__ __forceinline__ __half2 u2h2(uint32_t u) { return *(__half2*)&u; }
__device__ __forceinline__ uint32_t h22u(__half2 h) { return *(uint32_t*)&h; }

// ---------------- prep kernels -------------------------------------------------
__global__ __launch_bounds__(256) void x_to_h(
    const float* __restrict__ in, __half* __restrict__ out, int n4)
{
    int i = blockIdx.x * 256 + threadIdx.x;
    if (i >= n4) return;
    float4 v = ((const float4*)in)[i];
    uint2 o;
    o.x = pack2h(v.x, v.y);
    o.y = pack2h(v.z, v.w);
    ((uint2*)out)[i] = o;
}

__global__ __launch_bounds__(256) void wtrans4_kernel(
    const float* __restrict__ w0, const float* __restrict__ w1,
    const float* __restrict__ w2, const float* __restrict__ w3,
    __half* __restrict__ T)
{
    __shared__ float tile[32][33];
    const float* W = (blockIdx.z == 0) ? w0 : (blockIdx.z == 1) ? w1
                   : (blockIdx.z == 2) ? w2 : w3;
    __half* Tz = T + (size_t)blockIdx.z * WSZ;
    const int n0 = blockIdx.x * 32, k0 = blockIdx.y * 32;
    const int tx = threadIdx.x & 31, ty = threadIdx.x >> 5;
    #pragma unroll
    for (int r = 0; r < 4; r++)
        tile[ty + 8 * r][tx] = W[(size_t)(k0 + ty + 8 * r) * DMODEL + n0 + tx];
    __syncthreads();
    #pragma unroll
    for (int r = 0; r < 4; r++) {
        int n = n0 + ty + 8 * r, k = k0 + tx;
        Tz[(size_t)n * DMODEL + k] = __float2half(tile[tx][ty + 8 * r]);
    }
}

__global__ void bias_concat(const float* bq, const float* bk, const float* bv,
                            float* dst)
{
    int i = blockIdx.x * 256 + threadIdx.x;
    if (i < DMODEL) {
        dst[i] = bq[i];
        dst[DMODEL + i] = bk[i];
        dst[2 * DMODEL + i] = bv[i];
    }
}

// ---------------- fp16 GEMM: 128m x 128n CTA, 8 warps of 64x32, BK=64 ---------
// 3-stage cp.async pipeline, smem 108KB -> 2 CTAs per SM. (R13, proven)
#define BK3 64
#define ROW3 144
#define A_T3 (128 * ROW3)          // 18432
#define B_T3 (128 * ROW3)          // 18432
#define STG3 (A_T3 + B_T3)         // 36864
#define G3_SMEM (3 * STG3)         // 110592
#define NCH3 (DMODEL / BK3)        // 16
#define GT 256

__global__ __launch_bounds__(GT, 2) void gemm_h(
    const __half* __restrict__ A, const __half* __restrict__ B,
    const float* __restrict__ bias,
    __half* __restrict__ qkv, float* __restrict__ ofp, int mode)
{
    extern __shared__ char smem[];
    const uint32_t sbase = smem_u32(smem);
    const int tid = threadIdx.x;
    const int wid = tid >> 5, lane = tid & 31;
    const int n0 = blockIdx.x * 128;
    const int m0 = blockIdx.y * 128;

    const int warp_m = (wid & 1) * 64;
    const int warp_n = (wid >> 1) * 32;

    const __half* gA = A + (size_t)m0 * DMODEL;
    const __half* gB = B + (size_t)n0 * DMODEL;

    auto load_stage = [&](int st, int c) {
        const int k0 = c * BK3;
        const uint32_t stage = sbase + st * STG3;
        #pragma unroll
        for (int i = 0; i < 4; i++) {
            int idx = tid + i * GT;
            int row = idx >> 3, ch = idx & 7;
            CP_ASYNC16(stage + row * ROW3 + ch * 16,
                       gA + (size_t)row * DMODEL + k0 + ch * 8);
        }
        #pragma unroll
        for (int i = 0; i < 4; i++) {
            int idx = tid + i * GT;
            int row = idx >> 3, ch = idx & 7;
            CP_ASYNC16(stage + A_T3 + row * ROW3 + ch * 16,
                       gB + (size_t)row * DMODEL + k0 + ch * 8);
        }
    };

    float acc[4][4][4];
    #pragma unroll
    for (int i = 0; i < 4; i++)
        #pragma unroll
        for (int j = 0; j < 4; j++)
            #pragma unroll
            for (int q = 0; q < 4; q++) acc[i][j][q] = 0.f;

    load_stage(0, 0); CP_COMMIT();
    load_stage(1, 1); CP_COMMIT();

    const int a_r = lane & 15;
    const int a_c = (lane & 16) ? 16 : 0;
    const int b_r = ((lane & 16) ? 8 : 0) + (lane & 7);
    const int b_c = (lane & 8) ? 16 : 0;

    for (int c = 0; c < NCH3; c++) {
        if (c + 2 < NCH3) { CP_WAIT(1); } else { CP_WAIT(0); }
        __syncthreads();
        if (c + 2 < NCH3) { load_stage((c + 2) % 3, c + 2); CP_COMMIT(); }

        const uint32_t stage = sbase + (c % 3) * STG3;

        #pragma unroll
        for (int ks = 0; ks < 4; ks++) {
            uint32_t ah[4][4];
            #pragma unroll
            for (int mf = 0; mf < 4; mf++)
                ldsm_x4(ah[mf], stage + (warp_m + mf * 16 + a_r) * ROW3
                                 + ks * 32 + a_c);
            #pragma unroll
            for (int nfp = 0; nfp < 2; nfp++) {
                uint32_t bh[4];
                ldsm_x4(bh, stage + A_T3 + (warp_n + nfp * 16 + b_r) * ROW3
                             + ks * 32 + b_c);
                #pragma unroll
                for (int mf = 0; mf < 4; mf++) {
                    mma_f16(acc[mf][nfp * 2 + 0], ah[mf], bh + 0);
                    mma_f16(acc[mf][nfp * 2 + 1], ah[mf], bh + 2);
                }
            }
        }
    }

    // ---- epilogue ----
    #pragma unroll
    for (int mf = 0; mf < 4; mf++) {
        const int mA = m0 + warp_m + mf * 16 + (lane >> 2);
        #pragma unroll
        for (int nf = 0; nf < 4; nf++) {
            const int n = n0 + warp_n + nf * 8 + (lane & 3) * 2;
            const float b0 = bias[n], b1 = bias[n + 1];
            float v0 = acc[mf][nf][0] + b0;
            float v1 = acc[mf][nf][1] + b1;
            float v2 = acc[mf][nf][2] + b0;
            float v3 = acc[mf][nf][3] + b1;
            if (mode == 0) {
                int proj = n >> 10;
                int np = n & 1023;
                int h = np >> 6, d = np & 63;
                int bb0 = mA >> 11, s0 = mA & 2047;
                int m2 = mA + 8;
                int bb1 = m2 >> 11, s1 = m2 & 2047;
                size_t off = (size_t)proj * PSZ;
                size_t i0 = off + ((size_t)(bb0 * HEADS + h) * SEQ + s0) * DK + d;
                size_t i1 = off + ((size_t)(bb1 * HEADS + h) * SEQ + s1) * DK + d;
                if (proj == 0) { v0 *= 0.125f; v1 *= 0.125f; v2 *= 0.125f; v3 *= 0.125f; }
                *(uint32_t*)(qkv + i0) = pack2h(v0, v1);
                *(uint32_t*)(qkv + i1) = pack2h(v2, v3);
            } else {
                float2 w0 = {v0, v1}, w1 = {v2, v3};
                *(float2*)(ofp + (size_t)mA * DMODEL + n) = w0;
                *(float2*)(ofp + (size_t)(mA + 8) * DMODEL + n) = w1;
            }
        }
    }
}

// ---------------- fp16 HMMA flash attention, KV tile 64, 4-stage --------------
// Q 18KB + 4 x (K64+V64 = 18KB) = 92KB -> 2 CTAs/SM, prefetch distance 3.
// QK fp16-acc; fp16 softmax; P half2 fed straight into PV; fp32 O fold.
#define AT_RB 144
#define AT_Q  0u
#define AT_STG 18432u            // + st*18432: K(64x144), V(+9216)
#define AT_STGB 18432
#define AT_SMEM (18432 + 4 * AT_STGB)   // 92160

__global__ __launch_bounds__(256, 2) void attn_mma(
    const __half* __restrict__ Q, const __half* __restrict__ K,
    const __half* __restrict__ V, __half* __restrict__ Ao)
{
    extern __shared__ char smem[];
    const uint32_t sb = smem_u32(smem);
    const int tid = threadIdx.x, wid = tid >> 5, lane = tid & 31;
    const int qt = blockIdx.x, bh = blockIdx.y;
    const int q0 = qt * 128;
    const size_t base = (size_t)bh * SEQ * DK;

    const char* kv_src[2] = { (const char*)(K + base), (const char*)(V + base) };

    auto ld_q = [&] {
        #pragma unroll
        for (int i = 0; i < 4; i++) {
            int idx = tid + i * 256;              // 0..1023
            int r  = idx >> 3;
            int ch = idx & 7;
            CP_ASYNC16(sb + AT_Q + r * AT_RB + ch * 16,
                       (const char*)(Q + base + (size_t)(q0 + r) * DK) + ch * 16);
        }
    };
    // one chunk = 64 K rows + 64 V rows = 1024 16B-chunks -> 4/thread
    auto ld_kv = [&](int st, int t) {
        #pragma unroll
        for (int i = 0; i < 4; i++) {
            int idx = tid + i * 256;              // 0..1023
            int ts = idx >> 9;                    // 0 k, 1 v
            int r  = (idx >> 3) & 63;
            int ch = idx & 7;
            const char* sp = kv_src[ts] + (size_t)(t * 64 + r) * 128 + ch * 16;
            CP_ASYNC16(sb + AT_STG + st * AT_STGB + ts * 9216 + r * AT_RB + ch * 16, sp);
        }
    };

    ld_q(); ld_kv(0, 0); CP_COMMIT();
    ld_kv(1, 1); CP_COMMIT();
    ld_kv(2, 2); CP_COMMIT();

    const int a_r = lane & 15;
    const int a_c = (lane & 16) ? 16 : 0;
    const int bm = lane >> 3;
    const int b_r = (bm & 1) * 8 + (lane & 7);
    const int b_c = (bm >> 1) * 16;
    const int v_r = lane & 15;
    const int v_c = (lane & 16) ? 16 : 0;

    const int wq = wid * 16;
    uint32_t qf[4][4];

    float of[8][4];
    #pragma unroll
    for (int j = 0; j < 8; j++)
        #pragma unroll
        for (int q = 0; q < 4; q++) of[j][q] = 0.f;
    float mrow0 = -1e30f, mrow1 = -1e30f, lrow0 = 0.f, lrow1 = 0.f;

    for (int c = 0; c < 32; c++) {
        if (c + 3 < 32) { CP_WAIT(2); } else { CP_WAIT(0); }
        __syncthreads();
        if (c == 0) {
            #pragma unroll
            for (int t = 0; t < 4; t++)
                ldsm_x4(qf[t], sb + AT_Q + (wq + a_r) * AT_RB + t * 32 + a_c);
        }
        if (c + 3 < 32) { ld_kv((c + 3) & 3, c + 3); CP_COMMIT(); }

        const uint32_t kbuf = sb + AT_STG + (c & 3) * AT_STGB;
        const uint32_t vbuf = kbuf + 9216;

        // ---- S = Q K^T over 64 keys, fp16 accumulate ----
        uint32_t sf16[8][2];
        #pragma unroll
        for (int j = 0; j < 8; j++) { sf16[j][0] = 0u; sf16[j][1] = 0u; }

        #pragma unroll
        for (int t = 0; t < 4; t++) {
            #pragma unroll
            for (int g = 0; g < 4; g++) {
                uint32_t r4[4];
                ldsm_x4(r4, kbuf + (g * 16 + b_r) * AT_RB + t * 32 + b_c);
                uint32_t kfa[2] = { r4[0], r4[2] };
                uint32_t kfb[2] = { r4[1], r4[3] };
                mma_f16acc(sf16[2 * g + 0], qf[t], kfa);
                mma_f16acc(sf16[2 * g + 1], qf[t], kfb);
            }
        }

        // ---- softmax in fp16 ----
        __half2 hm0 = u2h2(sf16[0][0]), hm1 = u2h2(sf16[0][1]);
        #pragma unroll
        for (int j = 1; j < 8; j++) {
            hm0 = __hmax2(hm0, u2h2(sf16[j][0]));
            hm1 = __hmax2(hm1, u2h2(sf16[j][1]));
        }
        float tm0 = fmaxf(__low2float(hm0), __high2float(hm0));
        float tm1 = fmaxf(__low2float(hm1), __high2float(hm1));
        tm0 = fmaxf(tm0, __shfl_xor_sync(0xffffffffu, tm0, 1));
        tm0 = fmaxf(tm0, __shfl_xor_sync(0xffffffffu, tm0, 2));
        tm1 = fmaxf(tm1, __shfl_xor_sync(0xffffffffu, tm1, 1));
        tm1 = fmaxf(tm1, __shfl_xor_sync(0xffffffffu, tm1, 2));
        float mn0 = fmaxf(mrow0, tm0), mn1 = fmaxf(mrow1, tm1);
        float cor0 = __expf(mrow0 - mn0), cor1 = __expf(mrow1 - mn1);
        const __half2 mn0h = __float2half2_rn(mn0);
        const __half2 mn1h = __float2half2_rn(mn1);
        float rs0 = 0.f, rs1 = 0.f;
        #pragma unroll
        for (int j = 0; j < 8; j++) {
            __half2 p0 = h2exp(__hsub2(u2h2(sf16[j][0]), mn0h));
            __half2 p1 = h2exp(__hsub2(u2h2(sf16[j][1]), mn1h));
            sf16[j][0] = h22u(p0);
            sf16[j][1] = h22u(p1);
            rs0 += __low2float(p0) + __high2float(p0);
            rs1 += __low2float(p1) + __high2float(p1);
        }
        rs0 += __shfl_xor_sync(0xffffffffu, rs0, 1);
        rs0 += __shfl_xor_sync(0xffffffffu, rs0, 2);
        rs1 += __shfl_xor_sync(0xffffffffu, rs1, 1);
        rs1 += __shfl_xor_sync(0xffffffffu, rs1, 2);
        lrow0 = lrow0 * cor0 + rs0;
        lrow1 = lrow1 * cor1 + rs1;
        mrow0 = mn0; mrow1 = mn1;

        // ---- PV partial in fp16 accumulators (P = sf16 directly) ----
        uint32_t of16[8][2];
        #pragma unroll
        for (int j = 0; j < 8; j++) { of16[j][0] = 0u; of16[j][1] = 0u; }

        #pragma unroll
        for (int t = 0; t < 4; t++) {          // 4 k-steps of 16 over 64 keys
            uint32_t ph[4] = { sf16[2 * t][0], sf16[2 * t][1],
                               sf16[2 * t + 1][0], sf16[2 * t + 1][1] };
            #pragma unroll
            for (int g = 0; g < 4; g++) {
                uint32_t r4[4];
                ldsm_x4_t(r4, vbuf + (t * 16 + v_r) * AT_RB + g * 32 + v_c);
                uint32_t vfa[2] = { r4[0], r4[1] };
                uint32_t vfb[2] = { r4[2], r4[3] };
                mma_f16acc(of16[2 * g + 0], ph, vfa);
                mma_f16acc(of16[2 * g + 1], ph, vfb);
            }
        }

        // ---- fold partial into fp32 with correction ----
        #pragma unroll
        for (int j = 0; j < 8; j++) {
            __half2 p0 = u2h2(of16[j][0]);
            __half2 p1 = u2h2(of16[j][1]);
            of[j][0] = of[j][0] * cor0 + __low2float(p0);
            of[j][1] = of[j][1] * cor0 + __high2float(p0);
            of[j][2] = of[j][2] * cor1 + __low2float(p1);
            of[j][3] = of[j][3] * cor1 + __high2float(p1);
        }
    }

    // ---- epilogue: fp16 out [B, S, H*Dk] ----
    const float inv0 = 1.f / lrow0, inv1 = 1.f / lrow1;
    const int r0 = q0 + wq + (lane >> 2), r1 = r0 + 8;
    const int b_ = bh >> 4, h_ = bh & 15;
    #pragma unroll
    for (int j = 0; j < 8; j++) {
        int d = j * 8 + (lane & 3) * 2;
        size_t i0 = ((size_t)b_ * SEQ + r0) * DMODEL + h_ * 64 + d;
        size_t i1 = ((size_t)b_ * SEQ + r1) * DMODEL + h_ * 64 + d;
        *(uint32_t*)(Ao + i0) = pack2h(of[j][0] * inv0, of[j][1] * inv0);
        *(uint32_t*)(Ao + i1) = pack2h(of[j][2] * inv1, of[j][3] * inv1);
    }
}

// ---------------------------------------------------------------------------
// Launch
// ---------------------------------------------------------------------------
extern "C" void kernel_launch(void* const* d_in, const int* in_sizes, int n_in,
                              void* d_out, int out_size)
{
    const float* x  = (const float*)d_in[0];
    const float* wq = (const float*)d_in[1];
    const float* bq = (const float*)d_in[2];
    const float* wk = (const float*)d_in[3];
    const float* bk = (const float*)d_in[4];
    const float* wv = (const float*)d_in[5];
    const float* bv = (const float*)d_in[6];
    const float* wo = (const float*)d_in[7];
    const float* bo = (const float*)d_in[8];
    float* out = (float*)d_out;

    __half *xh, *wt, *qkv, *aoh;
    float* bias3;
    cudaGetSymbolAddress((void**)&xh,    g_xh);
    cudaGetSymbolAddress((void**)&wt,    g_wt);
    cudaGetSymbolAddress((void**)&qkv,   g_qkv);
    cudaGetSymbolAddress((void**)&aoh,   g_aoh);
    cudaGetSymbolAddress((void**)&bias3, g_bias);

    cudaFuncSetAttribute(gemm_h,
                         cudaFuncAttributeMaxDynamicSharedMemorySize, G3_SMEM);
    cudaFuncSetAttribute(attn_mma,
                         cudaFuncAttributeMaxDynamicSharedMemorySize, AT_SMEM);

    // 1. prep
    int n4 = PSZ / 4;
    x_to_h<<<(n4 + 255) / 256, 256>>>(x, xh, n4);
    dim3 tgrid(DMODEL / 32, DMODEL / 32, 4);
    wtrans4_kernel<<<tgrid, 256>>>(wq, wk, wv, wo, wt);
    bias_concat<<<(DMODEL + 255) / 256, 256>>>(bq, bk, bv, bias3);

    // 2. fused QKV projection (N=3072) -> fp16 q,k,v
    dim3 qkv_grid(3 * DMODEL / 128, MROWS / 128);   // (24, 64)
    gemm_h<<<qkv_grid, GT, G3_SMEM>>>(xh, wt, bias3, qkv, nullptr, 0);

    // 3. attention (KV64, 4-stage, 2 CTAs/SM, fp16 softmax)
    dim3 agrid(SEQ / 128, BATCH * HEADS);   // (16, 64)
    attn_mma<<<agrid, 256, AT_SMEM>>>(qkv, qkv + PSZ, qkv + 2 * PSZ, aoh);

    // 4. final projection (N=1024) -> fp32 out
    dim3 ogrid(DMODEL / 128, MROWS / 128);   // (8, 64)
    gemm_h<<<ogrid, GT, G3_SMEM>>>(aoh, wt + 3 * WSZ, bo, nullptr, out, 1);
}

// round 16
// speedup vs baseline: 1.0541x; 1.0541x over previous
#include <cuda_runtime.h>
#include <cuda_fp16.h>
#include <cstdint>

// ---------------------------------------------------------------------------
// MultiHeadAttention: B=4, S=2048, D=1024, H=16, Dk=64, fp32.
// Round 16: attention reverted to R13 (best: 481.8us). Prep kernels fused
// into one launch. Model: all mma.sync paths capped ~310 TF/s on sm_103a;
// 33.6M HMMA -> ~440us floor; this round harvests launch/prep overhead.
// ---------------------------------------------------------------------------

#define BATCH 4
#define SEQ   2048
#define DMODEL 1024
#define HEADS 16
#define DK    64
#define MROWS (BATCH * SEQ)          // 8192
#define WSZ   (DMODEL * DMODEL)
#define PSZ   (MROWS * DMODEL)

// ---------------- scratch ----------------------------------------------------
__device__ __align__(128) __half g_xh[PSZ];                  // x fp16
__device__ __align__(128) __half g_wt[4 * WSZ];              // W^T fp16: q,k,v,o
__device__ __align__(128) __half g_qkv[3 * PSZ];             // q,k,v fp16 [bh,s,d]
__device__ __align__(128) __half g_aoh[PSZ];                 // attn out fp16 [B,S,D]
__device__ __align__(128) float g_bias[3 * DMODEL];

// ---------------- PTX helpers ------------------------------------------------
__device__ __forceinline__ uint32_t smem_u32(const void* p) {
    uint32_t a;
    asm("{ .reg .u64 t; cvta.to.shared.u64 t, %1; cvt.u32.u64 %0, t; }"
        : "=r"(a) : "l"(p));
    return a;
}
__device__ __forceinline__ void ldsm_x4(uint32_t* r, uint32_t addr) {
    asm volatile("ldmatrix.sync.aligned.m8n8.x4.shared.b16 {%0,%1,%2,%3}, [%4];"
        : "=r"(r[0]), "=r"(r[1]), "=r"(r[2]), "=r"(r[3]) : "r"(addr));
}
__device__ __forceinline__ void ldsm_x4_t(uint32_t* r, uint32_t addr) {
    asm volatile("ldmatrix.sync.aligned.m8n8.x4.trans.shared.b16 {%0,%1,%2,%3}, [%4];"
        : "=r"(r[0]), "=r"(r[1]), "=r"(r[2]), "=r"(r[3]) : "r"(addr));
}
__device__ __forceinline__ void mma_f16(float* c, const uint32_t* a, const uint32_t* b) {
    asm volatile(
        "mma.sync.aligned.m16n8k16.row.col.f32.f16.f16.f32 "
        "{%0,%1,%2,%3}, {%4,%5,%6,%7}, {%8,%9}, {%0,%1,%2,%3};"
        : "+f"(c[0]), "+f"(c[1]), "+f"(c[2]), "+f"(c[3])
        : "r"(a[0]), "r"(a[1]), "r"(a[2]), "r"(a[3]), "r"(b[0]), "r"(b[1]));
}
__device__ __forceinline__ void mma_f16acc(uint32_t* c, const uint32_t* a, const uint32_t* b) {
    asm volatile(
        "mma.sync.aligned.m16n8k16.row.col.f16.f16.f16.f16 "
        "{%0,%1}, {%2,%3,%4,%5}, {%6,%7}, {%0,%1};"
        : "+r"(c[0]), "+r"(c[1])
        : "r"(a[0]), "r"(a[1]), "r"(a[2]), "r"(a[3]), "r"(b[0]), "r"(b[1]));
}
#define CP_ASYNC16(dst, src) \
    asm volatile("cp.async.cg.shared.global [%0], [%1], 16;" \
                 :: "r"(dst), "l"(src))
#define CP_COMMIT() asm volatile("cp.async.commit_group;" ::: "memory")
#define CP_WAIT(n)  asm volatile("cp.async.wait_group %0;" :: "n"(n) : "memory")

__device__ __forceinline__ uint32_t pack2h(float a, float b) {
    __half2 t = __floats2half2_rn(a, b);
    return *(uint32_t*)&t;
}

// ---------------- fused prep kernel -------------------------------------------
// blocks [0, 8192):        x fp32 -> fp16 (one float4 per thread)
// blocks [8192, 12288):    weight transpose+convert (1024 blocks per weight)
// block  12288:            bias concat
__global__ __launch_bounds__(256) void prep_kernel(
    const float* __restrict__ x,
    const float* __restrict__ w0, const float* __restrict__ w1,
    const float* __restrict__ w2, const float* __restrict__ w3,
    const float* __restrict__ bq, const float* __restrict__ bk,
    const float* __restrict__ bv,
    __half* __restrict__ xh, __half* __restrict__ wt, float* __restrict__ bias3)
{
    const int b = blockIdx.x;
    if (b < 8192) {
        int i = b * 256 + threadIdx.x;          // < 2,097,152 = PSZ/4
        float4 v = ((const float4*)x)[i];
        uint2 o;
        o.x = pack2h(v.x, v.y);
        o.y = pack2h(v.z, v.w);
        ((uint2*)xh)[i] = o;
    } else if (b < 12288) {
        __shared__ float tile[32][33];
        int idx = b - 8192;
        int z = idx >> 10;                       // weight index 0..3
        int t2 = idx & 1023;
        const float* W = (z == 0) ? w0 : (z == 1) ? w1 : (z == 2) ? w2 : w3;
        __half* Tz = wt + (size_t)z * WSZ;
        const int n0 = (t2 & 31) * 32, k0 = (t2 >> 5) * 32;
        const int tx = threadIdx.x & 31, ty = threadIdx.x >> 5;
        #pragma unroll
        for (int r = 0; r < 4; r++)
            tile[ty + 8 * r][tx] = W[(size_t)(k0 + ty + 8 * r) * DMODEL + n0 + tx];
        __syncthreads();
        #pragma unroll
        for (int r = 0; r < 4; r++) {
            int n = n0 + ty + 8 * r, k = k0 + tx;
            Tz[(size_t)n * DMODEL + k] = __float2half(tile[tx][ty + 8 * r]);
        }
    } else {
        #pragma unroll
        for (int r = 0; r < 4; r++) {
            int i = threadIdx.x + r * 256;       // 0..1023
            bias3[i] = bq[i];
            bias3[DMODEL + i] = bk[i];
            bias3[2 * DMODEL + i] = bv[i];
        }
    }
}

// ---------------- fp16 GEMM: 128m x 128n CTA, 8 warps of 64x32, BK=64 ---------
// 3-stage cp.async pipeline, smem 108KB -> 2 CTAs per SM. (R13, proven)
#define BK3 64
#define ROW3 144
#define A_T3 (128 * ROW3)          // 18432
#define B_T3 (128 * ROW3)          // 18432
#define STG3 (A_T3 + B_T3)         // 36864
#define G3_SMEM (3 * STG3)         // 110592
#define NCH3 (DMODEL / BK3)        // 16
#define GT 256

__global__ __launch_bounds__(GT, 2) void gemm_h(
    const __half* __restrict__ A, const __half* __restrict__ B,
    const float* __restrict__ bias,
    __half* __restrict__ qkv, float* __restrict__ ofp, int mode)
{
    extern __shared__ char smem[];
    const uint32_t sbase = smem_u32(smem);
    const int tid = threadIdx.x;
    const int wid = tid >> 5, lane = tid & 31;
    const int n0 = blockIdx.x * 128;
    const int m0 = blockIdx.y * 128;

    const int warp_m = (wid & 1) * 64;
    const int warp_n = (wid >> 1) * 32;

    const __half* gA = A + (size_t)m0 * DMODEL;
    const __half* gB = B + (size_t)n0 * DMODEL;

    auto load_stage = [&](int st, int c) {
        const int k0 = c * BK3;
        const uint32_t stage = sbase + st * STG3;
        #pragma unroll
        for (int i = 0; i < 4; i++) {
            int idx = tid + i * GT;
            int row = idx >> 3, ch = idx & 7;
            CP_ASYNC16(stage + row * ROW3 + ch * 16,
                       gA + (size_t)row * DMODEL + k0 + ch * 8);
        }
        #pragma unroll
        for (int i = 0; i < 4; i++) {
            int idx = tid + i * GT;
            int row = idx >> 3, ch = idx & 7;
            CP_ASYNC16(stage + A_T3 + row * ROW3 + ch * 16,
                       gB + (size_t)row * DMODEL + k0 + ch * 8);
        }
    };

    float acc[4][4][4];
    #pragma unroll
    for (int i = 0; i < 4; i++)
        #pragma unroll
        for (int j = 0; j < 4; j++)
            #pragma unroll
            for (int q = 0; q < 4; q++) acc[i][j][q] = 0.f;

    load_stage(0, 0); CP_COMMIT();
    load_stage(1, 1); CP_COMMIT();

    const int a_r = lane & 15;
    const int a_c = (lane & 16) ? 16 : 0;
    const int b_r = ((lane & 16) ? 8 : 0) + (lane & 7);
    const int b_c = (lane & 8) ? 16 : 0;

    for (int c = 0; c < NCH3; c++) {
        if (c + 2 < NCH3) { CP_WAIT(1); } else { CP_WAIT(0); }
        __syncthreads();
        if (c + 2 < NCH3) { load_stage((c + 2) % 3, c + 2); CP_COMMIT(); }

        const uint32_t stage = sbase + (c % 3) * STG3;

        #pragma unroll
        for (int ks = 0; ks < 4; ks++) {
            uint32_t ah[4][4];
            #pragma unroll
            for (int mf = 0; mf < 4; mf++)
                ldsm_x4(ah[mf], stage + (warp_m + mf * 16 + a_r) * ROW3
                                 + ks * 32 + a_c);
            #pragma unroll
            for (int nfp = 0; nfp < 2; nfp++) {
                uint32_t bh[4];
                ldsm_x4(bh, stage + A_T3 + (warp_n + nfp * 16 + b_r) * ROW3
                             + ks * 32 + b_c);
                #pragma unroll
                for (int mf = 0; mf < 4; mf++) {
                    mma_f16(acc[mf][nfp * 2 + 0], ah[mf], bh + 0);
                    mma_f16(acc[mf][nfp * 2 + 1], ah[mf], bh + 2);
                }
            }
        }
    }

    // ---- epilogue ----
    #pragma unroll
    for (int mf = 0; mf < 4; mf++) {
        const int mA = m0 + warp_m + mf * 16 + (lane >> 2);
        #pragma unroll
        for (int nf = 0; nf < 4; nf++) {
            const int n = n0 + warp_n + nf * 8 + (lane & 3) * 2;
            const float b0 = bias[n], b1 = bias[n + 1];
            float v0 = acc[mf][nf][0] + b0;
            float v1 = acc[mf][nf][1] + b1;
            float v2 = acc[mf][nf][2] + b0;
            float v3 = acc[mf][nf][3] + b1;
            if (mode == 0) {
                int proj = n >> 10;
                int np = n & 1023;
                int h = np >> 6, d = np & 63;
                int bb0 = mA >> 11, s0 = mA & 2047;
                int m2 = mA + 8;
                int bb1 = m2 >> 11, s1 = m2 & 2047;
                size_t off = (size_t)proj * PSZ;
                size_t i0 = off + ((size_t)(bb0 * HEADS + h) * SEQ + s0) * DK + d;
                size_t i1 = off + ((size_t)(bb1 * HEADS + h) * SEQ + s1) * DK + d;
                if (proj == 0) { v0 *= 0.125f; v1 *= 0.125f; v2 *= 0.125f; v3 *= 0.125f; }
                *(uint32_t*)(qkv + i0) = pack2h(v0, v1);
                *(uint32_t*)(qkv + i1) = pack2h(v2, v3);
            } else {
                float2 w0 = {v0, v1}, w1 = {v2, v3};
                *(float2*)(ofp + (size_t)mA * DMODEL + n) = w0;
                *(float2*)(ofp + (size_t)(mA + 8) * DMODEL + n) = w1;
            }
        }
    }
}

// ---------------- fp16 HMMA flash attention, KV tile 128 (R13 exact) ----------
// QK: fp16-acc HMMA, unpacked to fp32 before softmax. fp32 softmax.
// PV: fp16-acc partials folded per chunk. 3-stage cp.async pipeline, 1 CTA/SM.
#define AT_RB 144
#define AT_Q  0u
#define AT_STG 18432u            // + st*36864: K(128x144), V(+18432)
#define AT_STGB 36864
#define AT_SMEM (18432 + 3 * AT_STGB)   // 129024

__global__ __launch_bounds__(256, 1) void attn_mma(
    const __half* __restrict__ Q, const __half* __restrict__ K,
    const __half* __restrict__ V, __half* __restrict__ Ao)
{
    extern __shared__ char smem[];
    const uint32_t sb = smem_u32(smem);
    const int tid = threadIdx.x, wid = tid >> 5, lane = tid & 31;
    const int qt = blockIdx.x, bh = blockIdx.y;
    const int q0 = qt * 128;
    const size_t base = (size_t)bh * SEQ * DK;

    const char* kv_src[2] = { (const char*)(K + base), (const char*)(V + base) };

    auto ld_q = [&] {
        #pragma unroll
        for (int i = 0; i < 4; i++) {
            int idx = tid + i * 256;
            int r  = idx >> 3;
            int ch = idx & 7;
            CP_ASYNC16(sb + AT_Q + r * AT_RB + ch * 16,
                       (const char*)(Q + base + (size_t)(q0 + r) * DK) + ch * 16);
        }
    };
    auto ld_kv = [&](int st, int t) {
        #pragma unroll
        for (int i = 0; i < 8; i++) {
            int idx = tid + i * 256;
            int ts = idx >> 10;
            int r  = (idx >> 3) & 127;
            int ch = idx & 7;
            const char* sp = kv_src[ts] + (size_t)(t * 128 + r) * 128 + ch * 16;
            CP_ASYNC16(sb + AT_STG + st * AT_STGB + ts * 18432 + r * AT_RB + ch * 16, sp);
        }
    };

    ld_q(); ld_kv(0, 0); CP_COMMIT();
    ld_kv(1, 1); CP_COMMIT();

    const int a_r = lane & 15;
    const int a_c = (lane & 16) ? 16 : 0;
    const int bm = lane >> 3;
    const int b_r = (bm & 1) * 8 + (lane & 7);
    const int b_c = (bm >> 1) * 16;
    const int v_r = lane & 15;
    const int v_c = (lane & 16) ? 16 : 0;

    const int wq = wid * 16;
    uint32_t qf[4][4];

    float of[8][4];
    #pragma unroll
    for (int j = 0; j < 8; j++)
        #pragma unroll
        for (int q = 0; q < 4; q++) of[j][q] = 0.f;
    float mrow0 = -1e30f, mrow1 = -1e30f, lrow0 = 0.f, lrow1 = 0.f;

    for (int c = 0; c < 16; c++) {
        if (c + 2 < 16) { CP_WAIT(1); } else { CP_WAIT(0); }
        __syncthreads();
        if (c == 0) {
            #pragma unroll
            for (int t = 0; t < 4; t++)
                ldsm_x4(qf[t], sb + AT_Q + (wq + a_r) * AT_RB + t * 32 + a_c);
        }
        if (c + 2 < 16) { ld_kv((c + 2) % 3, c + 2); CP_COMMIT(); }

        const uint32_t kbuf = sb + AT_STG + (c % 3) * AT_STGB;
        const uint32_t vbuf = kbuf + 18432;

        // ---- S = Q K^T over 128 keys, fp16 accumulate ----
        uint32_t sf16[16][2];
        #pragma unroll
        for (int j = 0; j < 16; j++) { sf16[j][0] = 0u; sf16[j][1] = 0u; }

        #pragma unroll
        for (int t = 0; t < 4; t++) {
            uint32_t kf[16][2];
            #pragma unroll
            for (int g = 0; g < 8; g++) {
                uint32_t r4[4];
                ldsm_x4(r4, kbuf + (g * 16 + b_r) * AT_RB + t * 32 + b_c);
                kf[2*g][0] = r4[0]; kf[2*g][1] = r4[2];
                kf[2*g+1][0] = r4[1]; kf[2*g+1][1] = r4[3];
            }
            #pragma unroll
            for (int j = 0; j < 16; j++)
                mma_f16acc(sf16[j], qf[t], kf[j]);
        }

        // unpack fp16 scores -> fp32
        float sf[16][4];
        #pragma unroll
        for (int j = 0; j < 16; j++) {
            __half2 s0 = *(__half2*)&sf16[j][0];
            __half2 s1 = *(__half2*)&sf16[j][1];
            sf[j][0] = __low2float(s0); sf[j][1] = __high2float(s0);
            sf[j][2] = __low2float(s1); sf[j][3] = __high2float(s1);
        }

        // ---- online softmax (fp32) ----
        float tm0 = -1e30f, tm1 = -1e30f;
        #pragma unroll
        for (int j = 0; j < 16; j++) {
            tm0 = fmaxf(tm0, fmaxf(sf[j][0], sf[j][1]));
            tm1 = fmaxf(tm1, fmaxf(sf[j][2], sf[j][3]));
        }
        tm0 = fmaxf(tm0, __shfl_xor_sync(0xffffffffu, tm0, 1));
        tm0 = fmaxf(tm0, __shfl_xor_sync(0xffffffffu, tm0, 2));
        tm1 = fmaxf(tm1, __shfl_xor_sync(0xffffffffu, tm1, 1));
        tm1 = fmaxf(tm1, __shfl_xor_sync(0xffffffffu, tm1, 2));
        float mn0 = fmaxf(mrow0, tm0), mn1 = fmaxf(mrow1, tm1);
        float cor0 = __expf(mrow0 - mn0), cor1 = __expf(mrow1 - mn1);
        float rs0 = 0.f, rs1 = 0.f;
        #pragma unroll
        for (int j = 0; j < 16; j++) {
            sf[j][0] = __expf(sf[j][0] - mn0);
            sf[j][1] = __expf(sf[j][1] - mn0);
            sf[j][2] = __expf(sf[j][2] - mn1);
            sf[j][3] = __expf(sf[j][3] - mn1);
            rs0 += sf[j][0] + sf[j][1];
            rs1 += sf[j][2] + sf[j][3];
        }
        rs0 += __shfl_xor_sync(0xffffffffu, rs0, 1);
        rs0 += __shfl_xor_sync(0xffffffffu, rs0, 2);
        rs1 += __shfl_xor_sync(0xffffffffu, rs1, 1);
        rs1 += __shfl_xor_sync(0xffffffffu, rs1, 2);
        lrow0 = lrow0 * cor0 + rs0;
        lrow1 = lrow1 * cor1 + rs1;
        mrow0 = mn0; mrow1 = mn1;

        // ---- PV partial in fp16 accumulators ----
        uint32_t of16[8][2];
        #pragma unroll
        for (int j = 0; j < 8; j++) { of16[j][0] = 0u; of16[j][1] = 0u; }

        #pragma unroll
        for (int t = 0; t < 8; t++) {
            uint32_t ph[4];
            {
                const float* pa = sf[2 * t];
                const float* pb = sf[2 * t + 1];
                ph[0] = pack2h(pa[0], pa[1]);
                ph[1] = pack2h(pa[2], pa[3]);
                ph[2] = pack2h(pb[0], pb[1]);
                ph[3] = pack2h(pb[2], pb[3]);
            }
            uint32_t vf[8][2];
            #pragma unroll
            for (int g = 0; g < 4; g++) {
                uint32_t r4[4];
                ldsm_x4_t(r4, vbuf + (t * 16 + v_r) * AT_RB + g * 32 + v_c);
                vf[2*g][0] = r4[0]; vf[2*g][1] = r4[1];
                vf[2*g+1][0] = r4[2]; vf[2*g+1][1] = r4[3];
            }
            #pragma unroll
            for (int j = 0; j < 8; j++)
                mma_f16acc(of16[j], ph, vf[j]);
        }

        // ---- fold partial into fp32 with correction ----
        #pragma unroll
        for (int j = 0; j < 8; j++) {
            __half2 p0 = *(__half2*)&of16[j][0];
            __half2 p1 = *(__half2*)&of16[j][1];
            of[j][0] = of[j][0] * cor0 + __low2float(p0);
            of[j][1] = of[j][1] * cor0 + __high2float(p0);
            of[j][2] = of[j][2] * cor1 + __low2float(p1);
            of[j][3] = of[j][3] * cor1 + __high2float(p1);
        }
    }

    // ---- epilogue: fp16 out [B, S, H*Dk] ----
    const float inv0 = 1.f / lrow0, inv1 = 1.f / lrow1;
    const int r0 = q0 + wq + (lane >> 2), r1 = r0 + 8;
    const int b_ = bh >> 4, h_ = bh & 15;
    #pragma unroll
    for (int j = 0; j < 8; j++) {
        int d = j * 8 + (lane & 3) * 2;
        size_t i0 = ((size_t)b_ * SEQ + r0) * DMODEL + h_ * 64 + d;
        size_t i1 = ((size_t)b_ * SEQ + r1) * DMODEL + h_ * 64 + d;
        *(uint32_t*)(Ao + i0) = pack2h(of[j][0] * inv0, of[j][1] * inv0);
        *(uint32_t*)(Ao + i1) = pack2h(of[j][2] * inv1, of[j][3] * inv1);
    }
}

// ---------------------------------------------------------------------------
// Launch
// ---------------------------------------------------------------------------
extern "C" void kernel_launch(void* const* d_in, const int* in_sizes, int n_in,
                              void* d_out, int out_size)
{
    const float* x  = (const float*)d_in[0];
    const float* wq = (const float*)d_in[1];
    const float* bq = (const float*)d_in[2];
    const float* wk = (const float*)d_in[3];
    const float* bk = (const float*)d_in[4];
    const float* wv = (const float*)d_in[5];
    const float* bv = (const float*)d_in[6];
    const float* wo = (const float*)d_in[7];
    const float* bo = (const float*)d_in[8];
    float* out = (float*)d_out;

    __half *xh, *wt, *qkv, *aoh;
    float* bias3;
    cudaGetSymbolAddress((void**)&xh,    g_xh);
    cudaGetSymbolAddress((void**)&wt,    g_wt);
    cudaGetSymbolAddress((void**)&qkv,   g_qkv);
    cudaGetSymbolAddress((void**)&aoh,   g_aoh);
    cudaGetSymbolAddress((void**)&bias3, g_bias);

    cudaFuncSetAttribute(gemm_h,
                         cudaFuncAttributeMaxDynamicSharedMemorySize, G3_SMEM);
    cudaFuncSetAttribute(attn_mma,
                         cudaFuncAttributeMaxDynamicSharedMemorySize, AT_SMEM);

    // 1. fused prep (x conversion + 4 weight transposes + bias concat)
    prep_kernel<<<12289, 256>>>(x, wq, wk, wv, wo, bq, bk, bv, xh, wt, bias3);

    // 2. fused QKV projection (N=3072) -> fp16 q,k,v
    dim3 qkv_grid(3 * DMODEL / 128, MROWS / 128);   // (24, 64)
    gemm_h<<<qkv_grid, GT, G3_SMEM>>>(xh, wt, bias3, qkv, nullptr, 0);

    // 3. attention (R13: KV128, 3-stage, 1 CTA/SM, fp32 softmax)
    dim3 agrid(SEQ / 128, BATCH * HEADS);   // (16, 64)
    attn_mma<<<agrid, 256, AT_SMEM>>>(qkv, qkv + PSZ, qkv + 2 * PSZ, aoh);

    // 4. final projection (N=1024) -> fp32 out
    dim3 ogrid(DMODEL / 128, MROWS / 128);   // (8, 64)
    gemm_h<<<ogrid, GT, G3_SMEM>>>(aoh, wt + 3 * WSZ, bo, nullptr, out, 1);
}